// round 7
// baseline (speedup 1.0000x reference)
#include <cuda_runtime.h>
#include <cuda_bf16.h>

// SurvLoss, single fused persistent kernel.
// log(cumsum(exp)) is monotone => segment_max = value at LAST occurrence index.
//
// Phase A: stream 192MB; per-warp contiguous 2048-elem regions; smem
//          last-occurrence filter+atomicMax and count histogram; flush to
//          global; block exp-sums to g_block_agg; s1/obs scalars.
// Barrier: all 1024 blocks are co-resident (launch_bounds(256,8) => 1184
//          slots); last-arriving block scans block sums (double, exclusive)
//          and releases a flag; others nanosleep-spin.
// Phase B: each block finds segments whose GLOBAL last index lies in its own
//          tile (~1 expected), recomputes the partial exp-sum with all 256
//          threads, contributes max(log(prefix+partial),0)*cnt to g_s2.
// Final:   done-counter; last block writes the scalar + resets all state.

#define NUM_TIMES 1024
#define NBLK      1024
#define THREADS   256
#define ITERS     16
#define TILE      16384

__device__ float              g_block_agg[NBLK];
__device__ double             g_block_prefix[NBLK];
__device__ int                g_last[NUM_TIMES];      // 0 = empty, else idx+1
__device__ int                g_cnt[NUM_TIMES];
__device__ double             g_s1;
__device__ unsigned long long g_obs;
__device__ double             g_s2;
__device__ unsigned int       g_arrive;
__device__ unsigned int       g_release;
__device__ unsigned int       g_done2;

__global__ void __launch_bounds__(THREADS, 8)
fused_main(const float* __restrict__ outs,
           const int* __restrict__ T_E,
           const int* __restrict__ T_T,
           float* __restrict__ out) {
    __shared__ int   s_last[NUM_TIMES];
    __shared__ int   s_cnt[NUM_TIMES];
    __shared__ int   s_cand[NUM_TIMES];
    __shared__ float wtot[8];
    __shared__ float rs1[8];
    __shared__ int   rob[8];
    __shared__ int   s_flag;
    __shared__ int   s_ncand;

    const int b = blockIdx.x, tid = threadIdx.x;
    const int lane = tid & 31, w = tid >> 5;

    for (int i = tid; i < NUM_TIMES; i += THREADS) { s_last[i] = 0; s_cnt[i] = 0; }
    __syncthreads();

    const float4* o4 = (const float4*)outs;
    const int4*   e4 = (const int4*)T_E;
    const int4*   t4 = (const int4*)T_T;
    // warp w owns contiguous float4s [b*4096 + w*512, +512)
    const int wbase = b * (TILE / 4) + w * 512;

    float thr_tot = 0.f;
    float ls1 = 0.f;
    int   lob = 0;

    // ---- Phase A: streaming (reverse order: filter kills most atomicMax) ----
#pragma unroll 8
    for (int c = ITERS - 1; c >= 0; --c) {
        const int fi = wbase + c * 32 + lane;
        float4 v  = o4[fi];
        int4   tt = t4[fi];
        int4   te = e4[fi];

        thr_tot += __expf(v.x) + __expf(v.y) + __expf(v.z) + __expf(v.w);

        const int gi = fi * 4;
        // T_T in [0, NUM_TIMES) by construction
        int sg0 = tt.x, sg1 = tt.y, sg2 = tt.z, sg3 = tt.w;

        if (s_last[sg3] < gi + 4) atomicMax(&s_last[sg3], gi + 4);
        if (s_last[sg2] < gi + 3) atomicMax(&s_last[sg2], gi + 3);
        if (s_last[sg1] < gi + 2) atomicMax(&s_last[sg1], gi + 2);
        if (s_last[sg0] < gi + 1) atomicMax(&s_last[sg0], gi + 1);

        if (te.x) atomicAdd(&s_cnt[sg0], 1);
        if (te.y) atomicAdd(&s_cnt[sg1], 1);
        if (te.z) atomicAdd(&s_cnt[sg2], 1);
        if (te.w) atomicAdd(&s_cnt[sg3], 1);

        ls1 += te.x ? v.x : 0.f;
        ls1 += te.y ? v.y : 0.f;
        ls1 += te.z ? v.z : 0.f;
        ls1 += te.w ? v.w : 0.f;
        lob += te.x + te.y + te.z + te.w;
    }

    // block reductions
    float xx = thr_tot;
#pragma unroll
    for (int o = 16; o; o >>= 1) {
        xx  += __shfl_xor_sync(0xffffffffu, xx, o);
        ls1 += __shfl_xor_sync(0xffffffffu, ls1, o);
        lob += __shfl_xor_sync(0xffffffffu, lob, o);
    }
    if (lane == 0) { wtot[w] = xx; rs1[w] = ls1; rob[w] = lob; }
    __syncthreads();
    if (tid == 0) {
        float bt = 0.f, bs = 0.f; int bo = 0;
#pragma unroll
        for (int k = 0; k < 8; k++) { bt += wtot[k]; bs += rs1[k]; bo += rob[k]; }
        g_block_agg[b] = bt;
        atomicAdd(&g_s1, (double)bs);
        atomicAdd(&g_obs, (unsigned long long)bo);
    }

    // flush segment tables to global
    __syncthreads();
    for (int i = tid; i < NUM_TIMES; i += THREADS) {
        int m = s_last[i];
        if (m) atomicMax(&g_last[i], m);
        int cnt = s_cnt[i];
        if (cnt) atomicAdd(&g_cnt[i], cnt);
    }

    // ---- grid barrier (all blocks resident: 8/SM * 148 >= 1024) ----
    __threadfence();
    __syncthreads();
    if (tid == 0) s_flag = (atomicAdd(&g_arrive, 1u) == NBLK - 1u);
    __syncthreads();
    if (s_flag) {
        // last-arriving block: exclusive double scan of the 1024 block sums
        double v0 = (double)__ldcg(&g_block_agg[4 * tid + 0]);
        double v1 = (double)__ldcg(&g_block_agg[4 * tid + 1]);
        double v2 = (double)__ldcg(&g_block_agg[4 * tid + 2]);
        double v3 = (double)__ldcg(&g_block_agg[4 * tid + 3]);
        double c0 = v0, c1 = c0 + v1, c2 = c1 + v2, c3 = c2 + v3;

        double x = c3;
#pragma unroll
        for (int o = 1; o < 32; o <<= 1) {
            double y = __shfl_up_sync(0xffffffffu, x, o);
            if (lane >= o) x += y;
        }
        __shared__ double wsc[8];
        if (lane == 31) wsc[w] = x;
        __syncthreads();
        double wexcl = 0.0;
#pragma unroll
        for (int k = 0; k < 8; k++) if (k < w) wexcl += wsc[k];
        double excl = wexcl + (x - c3);

        g_block_prefix[4 * tid + 0] = excl;
        g_block_prefix[4 * tid + 1] = excl + c0;
        g_block_prefix[4 * tid + 2] = excl + c1;
        g_block_prefix[4 * tid + 3] = excl + c2;
        __syncthreads();
        if (tid == 0) { __threadfence(); atomicExch(&g_release, 1u); }
    } else {
        if (tid == 0) {
            while (atomicAdd(&g_release, 0u) == 0u) __nanosleep(64);
        }
        __syncthreads();
    }
    __threadfence();

    // ---- Phase B: handle segments whose global last index is in MY tile ----
    if (tid == 0) s_ncand = 0;
    __syncthreads();
    for (int t = tid; t < NUM_TIMES; t += THREADS) {
        int e = __ldcg(&g_last[t]);
        if (e > 0 && ((e - 1) >> 14) == b) {
            if (__ldcg(&g_cnt[t]) > 0) {
                int p = atomicAdd(&s_ncand, 1);
                s_cand[p] = t;
            }
        }
    }
    __syncthreads();

    const int nc = s_ncand;
    const float4* o4b = (const float4*)outs + b * (TILE / 4);
    for (int k = 0; k < nc; k++) {
        const int t   = s_cand[k];
        const int e   = __ldcg(&g_last[t]);
        const int cnt = __ldcg(&g_cnt[t]);
        const int r   = (e - 1) & 16383;
        const int ql  = r >> 2;
        const int rem = r & 3;

        float acc = 0.f;
#pragma unroll
        for (int j = 0; j < 16; j++) {
            const int q = tid + j * THREADS;
            if (q <= ql) {
                float4 v = o4b[q];
                float s = __expf(v.x);
                if (q < ql) {
                    s += __expf(v.y) + __expf(v.z) + __expf(v.w);
                } else {
                    if (rem >= 1) s += __expf(v.y);
                    if (rem >= 2) s += __expf(v.z);
                    if (rem >= 3) s += __expf(v.w);
                }
                acc += s;
            }
        }
#pragma unroll
        for (int o = 16; o; o >>= 1) acc += __shfl_xor_sync(0xffffffffu, acc, o);
        if (lane == 0) wtot[w] = acc;     // reuse wtot as scratch
        __syncthreads();
        if (tid == 0) {
            float pt = 0.f;
#pragma unroll
            for (int kk = 0; kk < 8; kk++) pt += wtot[kk];
            double total = g_block_prefix[b] + (double)pt;
            double y = log(total);
            if (y < 0.0) y = 0.0;
            atomicAdd(&g_s2, y * (double)cnt);
        }
        __syncthreads();
    }

    // ---- finalize: last block to complete Phase B writes the scalar ----
    __threadfence();
    if (tid == 0) s_flag = (atomicAdd(&g_done2, 1u) == NBLK - 1u);
    __syncthreads();
    if (s_flag) {
        // reset segment tables for the next graph replay
        for (int i = tid; i < NUM_TIMES; i += THREADS) {
            g_last[i] = 0;
            g_cnt[i]  = 0;
        }
        if (tid == 0) {
            double s2t = atomicAdd(&g_s2, 0.0);
            double s1t = atomicAdd(&g_s1, 0.0);
            unsigned long long obs = atomicAdd(&g_obs, 0ull);
            out[0] = (float)((s2t - s1t) / (double)obs);
            g_s2 = 0.0; g_s1 = 0.0; g_obs = 0ull;
            g_arrive = 0u; g_release = 0u; g_done2 = 0u;
        }
    }
}

// ---------------------------------------------------------------- launch
extern "C" void kernel_launch(void* const* d_in, const int* in_sizes, int n_in,
                              void* d_out, int out_size) {
    const float* outs = (const float*)d_in[0];
    const int*   T_E  = (const int*)d_in[1];
    const int*   T_T  = (const int*)d_in[2];
    float* out = (float*)d_out;

    fused_main<<<NBLK, THREADS>>>(outs, T_E, T_T, out);
}

// round 12
// speedup vs baseline: 55.8116x; 55.8116x over previous
#include <cuda_runtime.h>
#include <cuda_bf16.h>

// SurvLoss, single fused persistent kernel.
// log(cumsum(exp)) is monotone => segment_max = value at LAST occurrence index.
//
// Phase A: stream 192MB; warp w of block b owns contiguous elems
//          [b*16384 + w*2048, +2048); register exp-sum doubles as the span
//          sum (g_wsum). smem last-occurrence filter+atomicMax and count
//          histogram; flush; block sums to g_block_agg; s1/obs scalars.
// Barrier: all 1024 blocks co-resident (launch_bounds(256,8), 148*8=1184
//          slots); last arriver scans block sums (double, exclusive),
//          releases via atomicExch; others poll with volatile loads.
// Phase B: BLOCK-PER-SEGMENT (blockIdx.x = segment id) — last occurrences
//          cluster in the final tiles, so owner-tile scheduling serializes
//          (R8/R9's 15/16 bug came from capping that hot block's list).
//          partial = span sums before region + <=2048-elem recompute.
// Final:   done-counter; last block writes scalar + resets scalars.

#define NUM_TIMES 1024
#define NBLK      1024
#define THREADS   256
#define ITERS     16
#define TILE      16384

__device__ float              g_wsum[NBLK * 8];   // per-warp 2048-elem exp sums
__device__ float              g_block_agg[NBLK];
__device__ double             g_block_prefix[NBLK];
__device__ int                g_last[NUM_TIMES];  // 0 = empty, else idx+1
__device__ int                g_cnt[NUM_TIMES];
__device__ double             g_s1;
__device__ unsigned long long g_obs;
__device__ double             g_s2;
__device__ unsigned int       g_arrive;
__device__ unsigned int       g_done2;
__device__ __align__(128) volatile unsigned int g_release[32];

__global__ void __launch_bounds__(THREADS, 8)
fused_main(const float* __restrict__ outs,
           const int* __restrict__ T_E,
           const int* __restrict__ T_T,
           float* __restrict__ out) {
    __shared__ int   s_last[NUM_TIMES];
    __shared__ int   s_cnt[NUM_TIMES];
    __shared__ float wtot[8];
    __shared__ float rs1[8];
    __shared__ int   rob[8];
    __shared__ int   s_flag;
    __shared__ int   sh_e, sh_cnt;

    const int b = blockIdx.x, tid = threadIdx.x;
    const int lane = tid & 31, w = tid >> 5;

    for (int i = tid; i < NUM_TIMES; i += THREADS) { s_last[i] = 0; s_cnt[i] = 0; }
    __syncthreads();

    const float4* o4 = (const float4*)outs;
    const int4*   e4 = (const int4*)T_E;
    const int4*   t4 = (const int4*)T_T;
    // warp w owns contiguous float4s [b*4096 + w*512, +512)
    const int wbase = b * (TILE / 4) + w * 512;

    float thr_tot = 0.f;
    float ls1 = 0.f;
    int   lob = 0;

    // ---- Phase A: streaming (reverse order: filter kills most atomicMax) ----
#pragma unroll 8
    for (int c = ITERS - 1; c >= 0; --c) {
        const int fi = wbase + c * 32 + lane;
        float4 v  = o4[fi];
        int4   tt = t4[fi];
        int4   te = e4[fi];

        thr_tot += __expf(v.x) + __expf(v.y) + __expf(v.z) + __expf(v.w);

        const int gi = fi * 4;
        // T_T in [0, NUM_TIMES) by construction
        int sg0 = tt.x, sg1 = tt.y, sg2 = tt.z, sg3 = tt.w;

        if (s_last[sg3] < gi + 4) atomicMax(&s_last[sg3], gi + 4);
        if (s_last[sg2] < gi + 3) atomicMax(&s_last[sg2], gi + 3);
        if (s_last[sg1] < gi + 2) atomicMax(&s_last[sg1], gi + 2);
        if (s_last[sg0] < gi + 1) atomicMax(&s_last[sg0], gi + 1);

        if (te.x) atomicAdd(&s_cnt[sg0], 1);
        if (te.y) atomicAdd(&s_cnt[sg1], 1);
        if (te.z) atomicAdd(&s_cnt[sg2], 1);
        if (te.w) atomicAdd(&s_cnt[sg3], 1);

        ls1 += te.x ? v.x : 0.f;
        ls1 += te.y ? v.y : 0.f;
        ls1 += te.z ? v.z : 0.f;
        ls1 += te.w ? v.w : 0.f;
        lob += te.x + te.y + te.z + te.w;
    }

    // warp reduce: exp region sum (contiguous span), s1, obs
    float xx = thr_tot;
#pragma unroll
    for (int o = 16; o; o >>= 1) {
        xx  += __shfl_xor_sync(0xffffffffu, xx, o);
        ls1 += __shfl_xor_sync(0xffffffffu, ls1, o);
        lob += __shfl_xor_sync(0xffffffffu, lob, o);
    }
    if (lane == 0) {
        g_wsum[b * 8 + w] = xx;
        wtot[w] = xx; rs1[w] = ls1; rob[w] = lob;
    }
    __syncthreads();
    if (tid == 0) {
        float bt = 0.f, bs = 0.f; int bo = 0;
#pragma unroll
        for (int k = 0; k < 8; k++) { bt += wtot[k]; bs += rs1[k]; bo += rob[k]; }
        g_block_agg[b] = bt;
        atomicAdd(&g_s1, (double)bs);
        atomicAdd(&g_obs, (unsigned long long)bo);
    }

    // flush segment tables to global
    __syncthreads();
    for (int i = tid; i < NUM_TIMES; i += THREADS) {
        int m = s_last[i];
        if (m) atomicMax(&g_last[i], m);
        int cnt = s_cnt[i];
        if (cnt) atomicAdd(&g_cnt[i], cnt);
    }

    // ---- grid barrier (all 1024 blocks resident in wave 1) ----
    __threadfence();
    __syncthreads();
    if (tid == 0) s_flag = (atomicAdd(&g_arrive, 1u) == NBLK - 1u);
    __syncthreads();
    if (s_flag) {
        // last arriver: exclusive double scan of the 1024 block sums
        double v0 = (double)__ldcg(&g_block_agg[4 * tid + 0]);
        double v1 = (double)__ldcg(&g_block_agg[4 * tid + 1]);
        double v2 = (double)__ldcg(&g_block_agg[4 * tid + 2]);
        double v3 = (double)__ldcg(&g_block_agg[4 * tid + 3]);
        double c0 = v0, c1 = c0 + v1, c2 = c1 + v2, c3 = c2 + v3;

        double x = c3;
#pragma unroll
        for (int o = 1; o < 32; o <<= 1) {
            double y = __shfl_up_sync(0xffffffffu, x, o);
            if (lane >= o) x += y;
        }
        __shared__ double wsc[8];
        if (lane == 31) wsc[w] = x;
        __syncthreads();
        double wexcl = 0.0;
#pragma unroll
        for (int k = 0; k < 8; k++) if (k < w) wexcl += wsc[k];
        double excl = wexcl + (x - c3);

        g_block_prefix[4 * tid + 0] = excl;
        g_block_prefix[4 * tid + 1] = excl + c0;
        g_block_prefix[4 * tid + 2] = excl + c1;
        g_block_prefix[4 * tid + 3] = excl + c2;
        __syncthreads();
        if (tid == 0) {
            __threadfence();
            atomicExch((unsigned int*)&g_release[0], 1u);
        }
    } else {
        if (tid == 0) {
            int backoff = 32;
            while (g_release[0] == 0u) {        // cheap L2 reads, no atomic convoy
                __nanosleep(backoff);
                if (backoff < 1024) backoff <<= 1;
            }
        }
        __syncthreads();
    }
    __threadfence();

    // ---- Phase B: block b handles SEGMENT b (perfect balance) ----
    if (tid == 0) {
        sh_e   = __ldcg(&g_last[b]);
        sh_cnt = __ldcg(&g_cnt[b]);
        g_last[b] = 0;      // sole reader -> reset here for next replay
        g_cnt[b]  = 0;
    }
    __syncthreads();
    const int e = sh_e, cnt = sh_cnt;
    const bool active = (e > 0) && (cnt > 0);

    if (active) {
        const int idx = e - 1;
        const int bo  = idx >> 14;           // owning tile
        const int wr  = (idx >> 11) & 7;     // warp-region within tile
        const int r   = idx & 2047;          // last included elem within region
        const int ql  = r >> 2;              // last float4 (0..511)
        const int rem = r & 3;

        float acc = 0.f;
        if (tid < wr) acc = g_wsum[bo * 8 + tid];    // full regions before

        const float4* o4b = (const float4*)outs + bo * (TILE / 4) + wr * 512;
#pragma unroll
        for (int k = 0; k < 2; k++) {
            const int q = tid + k * THREADS;
            if (q <= ql) {
                float4 v = o4b[q];
                float s = __expf(v.x);
                if (q < ql) {
                    s += __expf(v.y) + __expf(v.z) + __expf(v.w);
                } else {
                    if (rem >= 1) s += __expf(v.y);
                    if (rem >= 2) s += __expf(v.z);
                    if (rem >= 3) s += __expf(v.w);
                }
                acc += s;
            }
        }
#pragma unroll
        for (int o = 16; o; o >>= 1) acc += __shfl_xor_sync(0xffffffffu, acc, o);
        if (lane == 0) wtot[w] = acc;        // reuse as scratch
        __syncthreads();
        if (tid == 0) {
            float pt = 0.f;
#pragma unroll
            for (int kk = 0; kk < 8; kk++) pt += wtot[kk];
            double total = g_block_prefix[bo] + (double)pt;
            double y = log(total);
            if (y < 0.0) y = 0.0;
            atomicAdd(&g_s2, y * (double)cnt);
        }
    }

    // ---- finalize ----
    __threadfence();
    __syncthreads();
    if (tid == 0) {
        if (atomicAdd(&g_done2, 1u) == NBLK - 1u) {
            double s2t = atomicAdd(&g_s2, 0.0);
            double s1t = atomicAdd(&g_s1, 0.0);
            unsigned long long obs = atomicAdd(&g_obs, 0ull);
            out[0] = (float)((s2t - s1t) / (double)obs);
            g_s2 = 0.0; g_s1 = 0.0; g_obs = 0ull;
            g_arrive = 0u; g_done2 = 0u;
            atomicExch((unsigned int*)&g_release[0], 0u);
        }
    }
}

// ---------------------------------------------------------------- launch
extern "C" void kernel_launch(void* const* d_in, const int* in_sizes, int n_in,
                              void* d_out, int out_size) {
    const float* outs = (const float*)d_in[0];
    const int*   T_E  = (const int*)d_in[1];
    const int*   T_T  = (const int*)d_in[2];
    float* out = (float*)d_out;

    fused_main<<<NBLK, THREADS>>>(outs, T_E, T_T, out);
}